// round 17
// baseline (speedup 1.0000x reference)
#include <cuda_runtime.h>
#include <cuda_bf16.h>
#include <cstdint>

// Problem constants
#define BB 8
#define SS 8192
#define DD 1024
#define NROWS (BB * SS)   // 65536 token rows
#define BINS 4096         // 12-bit buckets: sign + 8 exp + 3 mantissa bits
#define BSHIFT 20         // mono >> 20 -> 12-bit bucket
#define CAND_CAP 2048

// Scratch (allocation-free rule: __device__ global). No protocol state at all:
// g_scores entries for inactive tokens are never consumed (mask guards them).
__device__ float g_scores[NROWS];

__device__ __forceinline__ unsigned int mono_of(float s) {
    unsigned int bits = __float_as_uint(s);
    return (bits & 0x80000000u) ? ~bits : (bits | 0x80000000u);
}

// ---------------------------------------------------------------------------
// Kernel 1: scores for ACTIVE tokens only; FOUR consecutive rows per warp
// with per-row predicated loads -> ~26 outstanding LDG.128 per warp on
// average (MLP pressure despite inactive-row skips). No histogram here.
// ---------------------------------------------------------------------------
__global__ __launch_bounds__(256) void score_kernel(
    const float4* __restrict__ hidden,        // NROWS * 256 float4
    const unsigned int* __restrict__ active,  // NROWS 32-bit bools
    const float4* __restrict__ w4,            // 256 float4
    const float*  __restrict__ bias)
{
    int gwarp = (blockIdx.x * blockDim.x + threadIdx.x) >> 5;  // 0..NROWS/4-1
    int lane  = threadIdx.x & 31;

    const int r0 = gwarp * 4;
    const unsigned int a0 = active[r0];
    const unsigned int a1 = active[r0 + 1];
    const unsigned int a2 = active[r0 + 2];
    const unsigned int a3 = active[r0 + 3];
    if ((a0 | a1 | a2 | a3) == 0u) return;

    const float4* rp0 = hidden + (size_t)(r0    ) * (DD / 4);
    const float4* rp1 = hidden + (size_t)(r0 + 1) * (DD / 4);
    const float4* rp2 = hidden + (size_t)(r0 + 2) * (DD / 4);
    const float4* rp3 = hidden + (size_t)(r0 + 3) * (DD / 4);

    float acc0 = 0.f, acc1 = 0.f, acc2 = 0.f, acc3 = 0.f;

#pragma unroll
    for (int j = 0; j < 8; ++j) {
        const int idx = lane + j * 32;
        float4 w = w4[idx];
        if (a0) { float4 x = rp0[idx];
            acc0 = fmaf(x.x, w.x, acc0); acc0 = fmaf(x.y, w.y, acc0);
            acc0 = fmaf(x.z, w.z, acc0); acc0 = fmaf(x.w, w.w, acc0); }
        if (a1) { float4 x = rp1[idx];
            acc1 = fmaf(x.x, w.x, acc1); acc1 = fmaf(x.y, w.y, acc1);
            acc1 = fmaf(x.z, w.z, acc1); acc1 = fmaf(x.w, w.w, acc1); }
        if (a2) { float4 x = rp2[idx];
            acc2 = fmaf(x.x, w.x, acc2); acc2 = fmaf(x.y, w.y, acc2);
            acc2 = fmaf(x.z, w.z, acc2); acc2 = fmaf(x.w, w.w, acc2); }
        if (a3) { float4 x = rp3[idx];
            acc3 = fmaf(x.x, w.x, acc3); acc3 = fmaf(x.y, w.y, acc3);
            acc3 = fmaf(x.z, w.z, acc3); acc3 = fmaf(x.w, w.w, acc3); }
    }

    float b_val = *bias;   // L1-resident; hides under the shfl trees

#pragma unroll
    for (int o = 16; o > 0; o >>= 1) {
        acc0 += __shfl_down_sync(0xffffffffu, acc0, o);
        acc1 += __shfl_down_sync(0xffffffffu, acc1, o);
        acc2 += __shfl_down_sync(0xffffffffu, acc2, o);
        acc3 += __shfl_down_sync(0xffffffffu, acc3, o);
    }

    if (lane == 0) {
        if (a0) g_scores[r0    ] = acc0 + b_val;
        if (a1) g_scores[r0 + 1] = acc1 + b_val;
        if (a2) g_scores[r0 + 2] = acc2 + b_val;
        if (a3) g_scores[r0 + 3] = acc3 + b_val;
    }
}

// ---------------------------------------------------------------------------
// Kernel 2 (grid=8, 1024 threads, ONE CTA per batch row, NO global protocol):
//   preload 8 tokens/thread with wide loads (2x uint4 mask + 2x float4 score)
//   build 4096-bin histogram in SMEM from the register-resident tokens
//   LDS scan -> (pivot, m); candidates from registers into smem; rank; store
//   outputs as 2x float4 per thread (fully coalesced). No global hist at all.
// ---------------------------------------------------------------------------
__global__ __launch_bounds__(1024) void select_kernel(
    const unsigned int* __restrict__ active,  // [BB, SS]
    float* __restrict__ out)                  // [BB, SS] bool as float32
{
    __shared__ unsigned int sh_hist[BINS];            // 16 KB
    __shared__ unsigned int warp_sums[32];
    __shared__ int s_n;
    __shared__ int s_pivot;
    __shared__ unsigned int s_m;
    __shared__ int s_cnt;
    __shared__ unsigned long long s_cand[CAND_CAP];   // 16 KB

    const int row  = blockIdx.x;
    const int tid  = threadIdx.x;
    const int lane = tid & 31;
    const int wid  = tid >> 5;

    const unsigned int* am = active   + (size_t)row * SS;
    const float*        sc = g_scores + (size_t)row * SS;
    float*              op = out      + (size_t)row * SS;

    // ---- preload this thread's 8 tokens (base = tid*8) ----
    const int base = tid * 8;
    uint4  m0 = ((const uint4*) am)[2 * tid];
    uint4  m1 = ((const uint4*) am)[2 * tid + 1];
    float4 v0 = ((const float4*)sc)[2 * tid];
    float4 v1 = ((const float4*)sc)[2 * tid + 1];

    unsigned int actv[8] = { m0.x, m0.y, m0.z, m0.w, m1.x, m1.y, m1.z, m1.w };
    float        sval[8] = { v0.x, v0.y, v0.z, v0.w, v1.x, v1.y, v1.z, v1.w };
    unsigned int mono[8];
#pragma unroll
    for (int j = 0; j < 8; ++j) mono[j] = mono_of(sval[j]);

    // ---- build histogram in SMEM ----
    ((uint4*)sh_hist)[tid] = make_uint4(0u, 0u, 0u, 0u);   // 4 bins/thread
    if (tid == 0) { s_cnt = 0; s_pivot = 0; s_m = 0u; }
    __syncthreads();
#pragma unroll
    for (int j = 0; j < 8; ++j)
        if (actv[j] != 0u)
            atomicAdd(&sh_hist[mono[j] >> BSHIFT], 1u);
    __syncthreads();

    // ---- suffix scan over descending bins -> (pivot, m) ----
    // thread t covers bins [(1023-t)*4 .. +3]; ascending t == descending bins
    uint4 h = ((const uint4*)sh_hist)[1023 - tid];
    unsigned int S = h.x + h.y + h.z + h.w;

    unsigned int inc = S;
#pragma unroll
    for (int o = 1; o < 32; o <<= 1) {
        unsigned int v = __shfl_up_sync(0xffffffffu, inc, o);
        if (lane >= o) inc += v;
    }
    if (lane == 31) warp_sums[wid] = inc;
    __syncthreads();
    if (wid == 0) {
        unsigned int w = warp_sums[lane];
        unsigned int wi = w;
#pragma unroll
        for (int o = 1; o < 32; o <<= 1) {
            unsigned int v = __shfl_up_sync(0xffffffffu, wi, o);
            if (lane >= o) wi += v;
        }
        warp_sums[lane] = wi - w;
        if (lane == 31) s_n = (int)wi;
    }
    __syncthreads();
    inc += warp_sums[wid];
    const unsigned int exc = inc - S;

    const int n_active = s_n;
    if (n_active == 0) {
        float4 z = make_float4(0.f, 0.f, 0.f, 0.f);
        ((float4*)op)[2 * tid]     = z;
        ((float4*)op)[2 * tid + 1] = z;
        return;
    }
    const unsigned int kk = (unsigned int)max(1, (n_active + 1) >> 1);

    if (exc < kk && kk <= inc) {   // exactly one thread owns the pivot
        int bin_base = (1023 - tid) * 4;
        unsigned int cum = exc;
        unsigned int v[4] = { h.w, h.z, h.y, h.x };   // descending bins
#pragma unroll
        for (int j = 0; j < 4; ++j) {
            if (cum + v[j] >= kk) { s_pivot = bin_base + 3 - j; s_m = kk - cum; break; }
            cum += v[j];
        }
    }
    __syncthreads();
    const int pivot = s_pivot;
    const unsigned int m = s_m;

    // ---- push pivot-bucket candidates from registers into smem ----
    int bkt[8];
    bool cnd[8];
#pragma unroll
    for (int j = 0; j < 8; ++j) {
        bkt[j] = (int)(mono[j] >> BSHIFT);
        cnd[j] = (actv[j] != 0u) && (bkt[j] == pivot);
        if (cnd[j]) {
            int p = atomicAdd(&s_cnt, 1);
            if (p < CAND_CAP)
                s_cand[p] = (((unsigned long long)mono[j]) << 32)
                          | (unsigned long long)(0xFFFFFFFFu - (unsigned)(base + j));
        }
    }
    __syncthreads();
    const int C = min(s_cnt, CAND_CAP);

    // ---- decide all 8 tokens; rank own candidates against smem list ----
    float r[8];
#pragma unroll
    for (int j = 0; j < 8; ++j) {
        if (actv[j] == 0u) { r[j] = 0.0f; continue; }
        if (bkt[j] > pivot) { r[j] = 1.0f; continue; }
        if (!cnd[j])        { r[j] = 0.0f; continue; }
        unsigned long long key = (((unsigned long long)mono[j]) << 32)
                               | (unsigned long long)(0xFFFFFFFFu - (unsigned)(base + j));
        unsigned int rank = 0;
        for (int q = 0; q < C; ++q)
            rank += (s_cand[q] > key);
        r[j] = (rank < m) ? 1.0f : 0.0f;
    }

    // ---- coalesced wide stores ----
    ((float4*)op)[2 * tid]     = make_float4(r[0], r[1], r[2], r[3]);
    ((float4*)op)[2 * tid + 1] = make_float4(r[4], r[5], r[6], r[7]);
}

// ---------------------------------------------------------------------------
extern "C" void kernel_launch(void* const* d_in, const int* in_sizes, int n_in,
                              void* d_out, int out_size)
{
    const float4*       hidden = (const float4*)d_in[0];
    const unsigned int* mask   = (const unsigned int*)d_in[1];
    const float4*       w4     = (const float4*)d_in[2];
    const float*        bias   = (const float*)d_in[3];
    float*              out    = (float*)d_out;

    score_kernel<<<(NROWS / 4) / 8, 256>>>(hidden, mask, w4, bias);
    select_kernel<<<BB, 1024>>>(mask, out);
}